// round 1
// baseline (speedup 1.0000x reference)
#include <cuda_runtime.h>

// ---------------------------------------------------------------------------
// Problem constants
// ---------------------------------------------------------------------------
#define HH 80
#define WW 96
#define TTT 112
#define NS (HH*WW*TTT)        // 860160 voxels
#define NC 16
#define NCC 59                // 2*C + 27
#define FH 40
#define FW 48
#define FT 56
// extended box(y) grid: centers in [-2, H+2) etc.
#define PH 84
#define PW 100
#define PT 116
#define NSP (PH*PW*PT)        // 974400

// ---------------------------------------------------------------------------
// Scratch (device globals; no allocation allowed)
// ---------------------------------------------------------------------------
__device__ float g_stack[NCC*NS];   // [xw(16) | corr(27) | y(16)]
__device__ float g_pm[NC*NS];       // box3(xw), centered
__device__ float g_pf[NC*NSP];      // box3(y), centered, extended grid
__device__ float g_t1[NCC*NS];      // conv1a out
__device__ float g_h [NC*NS];       // h
__device__ float g_t2[NC*NS];       // conv2a out
__device__ float g_hr[NC*NS];       // h + res

__device__ float2 g_wp1a[NCC*27*30];
__device__ float2 g_wp1b[NCC*27*8];
__device__ float2 g_wp2a[NC*27*8];
__device__ float2 g_wp2b[NC*27*8];
__device__ float2 g_wpf [NC*27*2];

// ---------------------------------------------------------------------------
// Weight repack: w[Cout][Cin][27] -> wp[ci][tap][co_pair] (float2, zero pad)
// ---------------------------------------------------------------------------
__global__ void repack_kernel(const float* __restrict__ w, int which,
                              int cout, int cin, int cpairs)
{
    float2* wp;
    switch (which) {
        case 0: wp = g_wp1a; break;
        case 1: wp = g_wp1b; break;
        case 2: wp = g_wp2a; break;
        case 3: wp = g_wp2b; break;
        default: wp = g_wpf; break;
    }
    int idx = blockIdx.x*256 + threadIdx.x;
    int total = cin*27*cpairs;
    if (idx >= total) return;
    int cp  = idx % cpairs;
    int tap = (idx / cpairs) % 27;
    int ci  = idx / (cpairs*27);
    int co0 = 2*cp, co1 = 2*cp+1;
    float a = (co0 < cout) ? w[(co0*cin + ci)*27 + tap] : 0.0f;
    float b = (co1 < cout) ? w[(co1*cin + ci)*27 + tap] : 0.0f;
    wp[idx] = make_float2(a, b);
}

// ---------------------------------------------------------------------------
// Fused: flow upsample (align_corners, x2) + grid_sample(x) + copy y -> stack
// ---------------------------------------------------------------------------
__global__ void warp_kernel(const float* __restrict__ x,
                            const float* __restrict__ y,
                            const float* __restrict__ flow)
{
    int idx = blockIdx.x*256 + threadIdx.x;
    if (idx >= NS) return;
    int t = idx % TTT;
    int w = (idx / TTT) % WW;
    int h = idx / (TTT*WW);

    // trilinear upsample of flow (align_corners=True), scaled by 2
    float ph = h * (39.0f/79.0f);
    float pw = w * (47.0f/95.0f);
    float pt = t * (55.0f/111.0f);
    int ih = (int)ph; if (ih > FH-2) ih = FH-2;
    int iw = (int)pw; if (iw > FW-2) iw = FW-2;
    int it = (int)pt; if (it > FT-2) it = FT-2;
    float fh = ph - (float)ih;
    float fw = pw - (float)iw;
    float ft = pt - (float)it;

    float fu[3];
    #pragma unroll
    for (int c = 0; c < 3; c++) {
        const float* fc = flow + c*(FH*FW*FT) + (ih*FW + iw)*FT + it;
        float v000 = fc[0],        v001 = fc[1];
        float v010 = fc[FT],       v011 = fc[FT+1];
        float v100 = fc[FW*FT],    v101 = fc[FW*FT+1];
        float v110 = fc[FW*FT+FT], v111 = fc[FW*FT+FT+1];
        float a0 = v000*(1.0f-ft) + v001*ft;
        float a1 = v010*(1.0f-ft) + v011*ft;
        float a2 = v100*(1.0f-ft) + v101*ft;
        float a3 = v110*(1.0f-ft) + v111*ft;
        float b0 = a0*(1.0f-fw) + a1*fw;
        float b1 = a2*(1.0f-fw) + a3*fw;
        fu[c] = 2.0f*(b0*(1.0f-fh) + b1*fh);
    }

    // grid_sample of x, zeros padding, coords in voxel units
    float cx = (float)h + fu[0];
    float cy = (float)w + fu[1];
    float cz = (float)t + fu[2];
    float x0f = floorf(cx), y0f = floorf(cy), z0f = floorf(cz);
    float fx = cx - x0f, fy = cy - y0f, fz = cz - z0f;
    int x0 = (int)x0f, y0 = (int)y0f, z0 = (int)z0f;

    float acc[NC];
    #pragma unroll
    for (int c = 0; c < NC; c++) acc[c] = 0.0f;

    #pragma unroll
    for (int dx = 0; dx < 2; dx++)
    #pragma unroll
    for (int dy = 0; dy < 2; dy++)
    #pragma unroll
    for (int dz = 0; dz < 2; dz++) {
        int ix = x0+dx, iy = y0+dy, iz = z0+dz;
        if (ix < 0 || ix >= HH || iy < 0 || iy >= WW || iz < 0 || iz >= TTT) continue;
        float wgt = (dx ? fx : 1.0f-fx) * (dy ? fy : 1.0f-fy) * (dz ? fz : 1.0f-fz);
        const float* xp = x + (ix*WW + iy)*TTT + iz;
        #pragma unroll
        for (int c = 0; c < NC; c++) acc[c] += wgt * xp[c*NS];
    }

    #pragma unroll
    for (int c = 0; c < NC; c++) {
        g_stack[c*NS + idx]        = acc[c];
        g_stack[(43+c)*NS + idx]   = y[c*NS + idx];
    }
}

// ---------------------------------------------------------------------------
// box3 of xw (stack ch 0..15), centered, zero pad -> g_pm
// ---------------------------------------------------------------------------
__global__ void box_pm_kernel()
{
    int idx = blockIdx.x*256 + threadIdx.x;
    int c = blockIdx.y;
    if (idx >= NS) return;
    int t = idx % TTT;
    int w = (idx / TTT) % WW;
    int h = idx / (TTT*WW);
    const float* s = g_stack + c*NS;
    float acc = 0.0f;
    #pragma unroll
    for (int dh = -1; dh <= 1; dh++) {
        int gh = h + dh; if ((unsigned)gh >= HH) continue;
        #pragma unroll
        for (int dw = -1; dw <= 1; dw++) {
            int gw = w + dw; if ((unsigned)gw >= WW) continue;
            const float* row = s + (gh*WW + gw)*TTT;
            #pragma unroll
            for (int dt = -1; dt <= 1; dt++) {
                int gt = t + dt; if ((unsigned)gt >= TTT) continue;
                acc += row[gt];
            }
        }
    }
    g_pm[c*NS + idx] = acc;
}

// ---------------------------------------------------------------------------
// box3 of y, centered, on extended grid (center = coord - 2) -> g_pf
// ---------------------------------------------------------------------------
__global__ void box_pf_kernel(const float* __restrict__ y)
{
    int idx = blockIdx.x*256 + threadIdx.x;
    int c = blockIdx.y;
    if (idx >= NSP) return;
    int d = idx % PT;
    int b = (idx / PT) % PW;
    int a = idx / (PT*PW);
    int hc = a - 2, wc = b - 2, tc = d - 2;
    const float* s = y + c*NS;
    float acc = 0.0f;
    #pragma unroll
    for (int dh = -1; dh <= 1; dh++) {
        int gh = hc + dh; if ((unsigned)gh >= HH) continue;
        #pragma unroll
        for (int dw = -1; dw <= 1; dw++) {
            int gw = wc + dw; if ((unsigned)gw >= WW) continue;
            const float* row = s + (gh*WW + gw)*TTT;
            #pragma unroll
            for (int dt = -1; dt <= 1; dt++) {
                int gt = tc + dt; if ((unsigned)gt >= TTT) continue;
                acc += row[gt];
            }
        }
    }
    g_pf[c*NSP + idx] = acc;
}

// ---------------------------------------------------------------------------
// correlation: corr[o] = (1/27) sum_c pm[c] * pf_ext[c, voxel + (2i-2,2j-2,2k-2)]
// writes stack channels 16..42
// ---------------------------------------------------------------------------
__global__ void corr_kernel()
{
    int idx = blockIdx.x*128 + threadIdx.x;
    if (idx >= NS) return;
    int t = idx % TTT;
    int w = (idx / TTT) % WW;
    int h = idx / (TTT*WW);

    float pm[NC];
    #pragma unroll
    for (int c = 0; c < NC; c++) pm[c] = g_pm[c*NS + idx];

    int o = 0;
    for (int i = 0; i < 3; i++)
    for (int j = 0; j < 3; j++)
    for (int k = 0; k < 3; k++) {
        const float* p = g_pf + ((h + 2*i)*PW + (w + 2*j))*PT + (t + 2*k);
        float acc = 0.0f;
        #pragma unroll
        for (int c = 0; c < NC; c++) acc += pm[c] * p[c*NSP];
        g_stack[(16 + o)*NS + idx] = acc * (1.0f/27.0f);
        o++;
    }
}

// ---------------------------------------------------------------------------
// Direct 3x3x3 conv, pad 1. Tile 4(H)x8(W)x8(T), 256 threads, one voxel/thread.
// All Cout accumulated as f32x2 pairs (packed FFMA2). Weights pre-packed
// [ci][tap][co_pair] so the inner loop is broadcast LDS.64 + fma.rn.f32x2.
// ---------------------------------------------------------------------------
template<int CIN, int CP, int COUT, bool RELU, bool ADD>
__global__ void __launch_bounds__(256)
conv3_kernel(const float* __restrict__ in, const float2* __restrict__ wp,
             const float* __restrict__ bias, const float* __restrict__ addsrc,
             float* __restrict__ out)
{
    __shared__ float  s_in[6*10*10];
    __shared__ float2 s_w[27*CP];
    const int tid = threadIdx.x;
    const int t0 = blockIdx.x*8, w0 = blockIdx.y*8, h0 = blockIdx.z*4;
    const int lt = tid & 7, lw = (tid >> 3) & 7, lh = tid >> 6;

    unsigned long long acc[CP];
    #pragma unroll
    for (int i = 0; i < CP; i++) acc[i] = 0ull;

    for (int ci = 0; ci < CIN; ci++) {
        __syncthreads();
        const float* inc = in + ci*NS;
        for (int i = tid; i < 600; i += 256) {
            int it = i % 10, iw = (i/10) % 10, ih = i/100;
            int gh = h0 + ih - 1, gw = w0 + iw - 1, gt = t0 + it - 1;
            float v = 0.0f;
            if ((unsigned)gh < HH && (unsigned)gw < WW && (unsigned)gt < TTT)
                v = inc[(gh*WW + gw)*TTT + gt];
            s_in[i] = v;
        }
        const float2* wc = wp + ci*27*CP;
        for (int i = tid; i < 27*CP; i += 256) s_w[i] = wc[i];
        __syncthreads();

        const unsigned long long* wq = reinterpret_cast<const unsigned long long*>(s_w);
        #pragma unroll
        for (int tap = 0; tap < 27; tap++) {
            const int dt = tap % 3, dw = (tap/3) % 3, dh = tap/9;
            float v = s_in[((lh+dh)*10 + (lw+dw))*10 + (lt+dt)];
            unsigned int vu = __float_as_uint(v);
            unsigned long long vv;
            asm("mov.b64 %0, {%1, %1};" : "=l"(vv) : "r"(vu));
            #pragma unroll
            for (int cp = 0; cp < CP; cp++) {
                asm("fma.rn.f32x2 %0, %1, %2, %0;"
                    : "+l"(acc[cp]) : "l"(wq[tap*CP + cp]), "l"(vv));
            }
        }
    }

    const int vox = ((h0+lh)*WW + (w0+lw))*TTT + (t0+lt);
    #pragma unroll
    for (int cp = 0; cp < CP; cp++) {
        float r0 = __uint_as_float((unsigned int)(acc[cp] & 0xffffffffull));
        float r1 = __uint_as_float((unsigned int)(acc[cp] >> 32));
        const int co0 = 2*cp, co1 = 2*cp+1;
        if (co0 < COUT) {
            float r = r0 + bias[co0];
            if (RELU) r = fmaxf(r, 0.0f);
            if (ADD)  r += addsrc[co0*NS + vox];
            out[co0*NS + vox] = r;
        }
        if (co1 < COUT) {
            float r = r1 + bias[co1];
            if (RELU) r = fmaxf(r, 0.0f);
            if (ADD)  r += addsrc[co1*NS + vox];
            out[co1*NS + vox] = r;
        }
    }
}

// ---------------------------------------------------------------------------
// Launch
// ---------------------------------------------------------------------------
extern "C" void kernel_launch(void* const* d_in, const int* in_sizes, int n_in,
                              void* d_out, int out_size)
{
    const float* x    = (const float*)d_in[0];
    const float* y    = (const float*)d_in[1];
    const float* flow = (const float*)d_in[2];
    const float* w1a  = (const float*)d_in[3];
    const float* b1a  = (const float*)d_in[4];
    const float* w1b  = (const float*)d_in[5];
    const float* b1b  = (const float*)d_in[6];
    const float* w2a  = (const float*)d_in[7];
    const float* b2a  = (const float*)d_in[8];
    const float* w2b  = (const float*)d_in[9];
    const float* b2b  = (const float*)d_in[10];
    const float* wf   = (const float*)d_in[11];
    const float* bf   = (const float*)d_in[12];
    float* out = (float*)d_out;

    void *p_stack, *p_t1, *p_h, *p_t2, *p_hr;
    void *p_wp1a, *p_wp1b, *p_wp2a, *p_wp2b, *p_wpf;
    cudaGetSymbolAddress(&p_stack, g_stack);
    cudaGetSymbolAddress(&p_t1,    g_t1);
    cudaGetSymbolAddress(&p_h,     g_h);
    cudaGetSymbolAddress(&p_t2,    g_t2);
    cudaGetSymbolAddress(&p_hr,    g_hr);
    cudaGetSymbolAddress(&p_wp1a,  g_wp1a);
    cudaGetSymbolAddress(&p_wp1b,  g_wp1b);
    cudaGetSymbolAddress(&p_wp2a,  g_wp2a);
    cudaGetSymbolAddress(&p_wp2b,  g_wp2b);
    cudaGetSymbolAddress(&p_wpf,   g_wpf);

    // weight repack
    repack_kernel<<<(NCC*27*30 + 255)/256, 256>>>(w1a, 0, 59, 59, 30);
    repack_kernel<<<(NCC*27*8  + 255)/256, 256>>>(w1b, 1, 16, 59, 8);
    repack_kernel<<<(NC*27*8   + 255)/256, 256>>>(w2a, 2, 16, 16, 8);
    repack_kernel<<<(NC*27*8   + 255)/256, 256>>>(w2b, 3, 16, 16, 8);
    repack_kernel<<<(NC*27*2   + 255)/256, 256>>>(wf,  4,  3, 16, 2);

    // upsample + warp + y copy
    warp_kernel<<<(NS + 255)/256, 256>>>(x, y, flow);

    // box sums
    box_pm_kernel<<<dim3((NS + 255)/256, NC), 256>>>();
    box_pf_kernel<<<dim3((NSP + 255)/256, NC), 256>>>(y);

    // correlation -> stack ch 16..42
    corr_kernel<<<(NS + 127)/128, 128>>>();

    dim3 cgrid(TTT/8, WW/8, HH/4);   // 14, 12, 20

    // conv1a: stack(59) -> t1(59), no act
    conv3_kernel<59,30,59,false,false><<<cgrid, 256>>>(
        (const float*)p_stack, (const float2*)p_wp1a, b1a, nullptr, (float*)p_t1);
    // conv1b: t1(59) -> h(16), relu
    conv3_kernel<59,8,16,true,false><<<cgrid, 256>>>(
        (const float*)p_t1, (const float2*)p_wp1b, b1b, nullptr, (float*)p_h);
    // conv2a: h -> t2, no act
    conv3_kernel<16,8,16,false,false><<<cgrid, 256>>>(
        (const float*)p_h, (const float2*)p_wp2a, b2a, nullptr, (float*)p_t2);
    // conv2b: hr = h + relu(conv(t2))
    conv3_kernel<16,8,16,true,true><<<cgrid, 256>>>(
        (const float*)p_t2, (const float2*)p_wp2b, b2b, (const float*)p_h, (float*)p_hr);
    // convf: out = conv(hr, wf) + bf
    conv3_kernel<16,2,3,false,false><<<cgrid, 256>>>(
        (const float*)p_hr, (const float2*)p_wpf, bf, nullptr, out);
}